// round 4
// baseline (speedup 1.0000x reference)
#include <cuda_runtime.h>

#define B_    4
#define N_    200000
#define C_    64
#define H_    512
#define W_    512
#define HID   128
#define TILE  128
#define TPB   1563   // ceil(200000/128)

// Transposed grid scratch: [B][H][W][C], 256 MiB (__device__ global = legal scratch)
__device__ float g_t[(size_t)B_ * H_ * W_ * C_];

typedef unsigned long long ull;

__device__ __forceinline__ ull pk2(float lo, float hi) {
    ull r; asm("mov.b64 %0, {%1,%2};" : "=l"(r) : "f"(lo), "f"(hi)); return r;
}
__device__ __forceinline__ void fma2(ull& d, ull a, ull b) {
    asm("fma.rn.f32x2 %0, %1, %2, %0;" : "+l"(d) : "l"(a), "l"(b));
}
__device__ __forceinline__ float2 upk(ull v) {
    float2 f; asm("mov.b64 {%0,%1}, %2;" : "=f"(f.x), "=f"(f.y) : "l"(v)); return f;
}

// ---------------------------------------------------------------------------
// Kernel 1: transpose grid [B,C,H,W] -> g_t [B,H,W,C], coalesced both sides.
// ---------------------------------------------------------------------------
__global__ void transpose_kernel(const float* __restrict__ grid) {
    __shared__ float t[64][65];
    const int w0  = blockIdx.x * 64;
    const int h   = blockIdx.y;
    const int b   = blockIdx.z;
    const int tid = threadIdx.x;

    #pragma unroll
    for (int it = 0; it < 16; ++it) {
        int lin = it * 256 + tid;
        int c = lin >> 6;          // 0..63
        int w = lin & 63;          // 0..63
        t[w][c] = grid[(((size_t)b * C_ + c) * H_ + h) * W_ + (w0 + w)];
    }
    __syncthreads();
    float* dst = g_t + (((size_t)b * H_ + h) * W_ + w0) * C_;
    #pragma unroll
    for (int it = 0; it < 16; ++it) {
        int lin = it * 256 + tid;
        int w = lin >> 6;
        int c = lin & 63;
        dst[(size_t)w * C_ + c] = t[w][c];
    }
}

// ---------------------------------------------------------------------------
// Kernel 2: fused gather (bilinear sample) + MLP per 128-point tile.
//   SMEM: w1s [66*128] (row 65 zero-padded) | feat [128*66]  -> reused as h [128*130]
//         b1s [128] | w2s [128*4 as float4] | b2s [4]
// GEMM: 256 threads as 16x16, each computes 8 pts x 8 hidden with f32x2 FMAs.
// ---------------------------------------------------------------------------
__global__ void __launch_bounds__(256, 2) latent_kernel(
    const float* __restrict__ xyz,
    const float* __restrict__ w1,
    const float* __restrict__ b1,
    const float* __restrict__ w2,
    const float* __restrict__ b2,
    float* __restrict__ out)
{
    extern __shared__ float sm[];
    float* w1s  = sm;                 // 66*128 = 8448 floats
    float* feat = sm + 8448;          // 128*66 = 8448 floats
    float* hbuf = sm;                 // 128*130 = 16640 floats (reuse after GEMM)
    float* b1s  = sm + 16896;         // 128
    float* w2s  = sm + 17024;         // 512 (16B aligned)
    float* b2s  = sm + 17536;         // 4   (16B aligned)

    const int tid  = threadIdx.x;
    const int b    = blockIdx.x / TPB;
    const int tile = blockIdx.x % TPB;
    const int n0   = tile * TILE;
    const int npts = min(TILE, N_ - n0);

    // ---- load weights into SMEM ----
    for (int i = tid; i < 65 * 128; i += 256) w1s[i] = w1[i];
    for (int i = tid; i < 128; i += 256) { w1s[65 * 128 + i] = 0.0f; b1s[i] = b1[i]; }
    for (int i = tid; i < 512; i += 256) w2s[i] = w2[i];
    if (tid < 4) b2s[tid] = b2[tid];

    // ---- gather: each warp handles 16 points; lane l covers channels 2l,2l+1 ----
    const int warp = tid >> 5, lane = tid & 31;
    const float* gt = g_t + (size_t)b * H_ * W_ * C_;
    const int co = lane * 2;
    for (int s = 0; s < 16; ++s) {
        int pt = warp * 16 + s;
        float2 res = make_float2(0.0f, 0.0f);
        float zv = 0.0f;
        if (pt < npts) {
            int n = n0 + pt;
            const float* p = xyz + ((size_t)b * N_ + n) * 3;
            float px = p[0], py = p[1], pz = p[2];
            // reference: xy = xyz[:, [0,2]], z = xyz[:,1]
            float x = (px + 1.0f) * 0.5f * 511.0f;
            float y = (pz + 1.0f) * 0.5f * 511.0f;
            float x0f = floorf(x), y0f = floorf(y);
            float wx = x - x0f,  wy = y - y0f;
            int x0 = min(max((int)x0f, 0), 511);
            int x1 = min(x0 + 1, 511);
            int y0 = min(max((int)y0f, 0), 511);
            int y1 = min(y0 + 1, 511);
            const float* r0 = gt + (size_t)y0 * (W_ * C_);
            const float* r1 = gt + (size_t)y1 * (W_ * C_);
            float2 v00 = *(const float2*)(r0 + (size_t)x0 * C_ + co);
            float2 v01 = *(const float2*)(r0 + (size_t)x1 * C_ + co);
            float2 v10 = *(const float2*)(r1 + (size_t)x0 * C_ + co);
            float2 v11 = *(const float2*)(r1 + (size_t)x1 * C_ + co);
            float tx = 1.0f - wx, ty = 1.0f - wy;
            float topx = v00.x * tx + v01.x * wx;
            float topy = v00.y * tx + v01.y * wx;
            float botx = v10.x * tx + v11.x * wx;
            float boty = v10.y * tx + v11.y * wx;
            res.x = topx * ty + botx * wy;
            res.y = topy * ty + boty * wy;
            zv = py;
        }
        *(float2*)&feat[pt * 66 + co] = res;
        if (lane == 0) { feat[pt * 66 + 64] = zv; feat[pt * 66 + 65] = 0.0f; }
    }
    __syncthreads();

    // ---- GEMM layer 1: [128 x 66] @ [66 x 128], f32x2-packed accumulators ----
    const int tm = tid >> 4, tn = tid & 15;
    const int tm8 = tm * 8, tn8 = tn * 8;
    ull acc[8][4];
    {
        float2 bp0 = *(float2*)&b1s[tn8];
        float2 bp1 = *(float2*)&b1s[tn8 + 2];
        float2 bp2 = *(float2*)&b1s[tn8 + 4];
        float2 bp3 = *(float2*)&b1s[tn8 + 6];
        ull i0 = pk2(bp0.x, bp0.y), i1 = pk2(bp1.x, bp1.y);
        ull i2 = pk2(bp2.x, bp2.y), i3 = pk2(bp3.x, bp3.y);
        #pragma unroll
        for (int i = 0; i < 8; ++i) {
            acc[i][0] = i0; acc[i][1] = i1; acc[i][2] = i2; acc[i][3] = i3;
        }
    }
    #pragma unroll 1
    for (int k = 0; k < 66; k += 2) {
        float4 wa0 = *(float4*)&w1s[k * 128 + tn8];
        float4 wa1 = *(float4*)&w1s[k * 128 + tn8 + 4];
        float4 wb0 = *(float4*)&w1s[(k + 1) * 128 + tn8];
        float4 wb1 = *(float4*)&w1s[(k + 1) * 128 + tn8 + 4];
        ull wk0[4] = { pk2(wa0.x, wa0.y), pk2(wa0.z, wa0.w),
                       pk2(wa1.x, wa1.y), pk2(wa1.z, wa1.w) };
        ull wk1[4] = { pk2(wb0.x, wb0.y), pk2(wb0.z, wb0.w),
                       pk2(wb1.x, wb1.y), pk2(wb1.z, wb1.w) };
        #pragma unroll
        for (int i = 0; i < 8; ++i) {
            float2 f = *(float2*)&feat[(tm8 + i) * 66 + k];
            ull f0 = pk2(f.x, f.x);
            ull f1 = pk2(f.y, f.y);
            #pragma unroll
            for (int jp = 0; jp < 4; ++jp) {
                fma2(acc[i][jp], f0, wk0[jp]);
                fma2(acc[i][jp], f1, wk1[jp]);
            }
        }
    }
    __syncthreads();   // everyone done reading w1s/feat before hbuf overwrites them

    // ---- ReLU + stash hidden activations to SMEM (stride 130 avoids conflicts) ----
    #pragma unroll
    for (int i = 0; i < 8; ++i) {
        #pragma unroll
        for (int jp = 0; jp < 4; ++jp) {
            float2 v = upk(acc[i][jp]);
            float* hr = &hbuf[(tm8 + i) * 130 + tn8 + jp * 2];
            hr[0] = fmaxf(v.x, 0.0f);
            hr[1] = fmaxf(v.y, 0.0f);
        }
    }
    __syncthreads();

    // ---- layer 2: out[pt] = h[pt] @ w2 + b2 (one thread per point) ----
    if (tid < npts) {
        const int pt = tid;
        const float* hr = &hbuf[pt * 130];
        float4 bb = *(float4*)b2s;
        ull a01 = pk2(bb.x, bb.y), a23 = pk2(bb.z, bb.w);
        #pragma unroll 4
        for (int k = 0; k < 128; ++k) {
            float hv = hr[k];
            float4 w = *(float4*)&w2s[k * 4];
            ull hh = pk2(hv, hv);
            fma2(a01, hh, pk2(w.x, w.y));
            fma2(a23, hh, pk2(w.z, w.w));
        }
        float2 o01 = upk(a01), o23 = upk(a23);
        int n = n0 + pt;
        *(float4*)&out[((size_t)b * N_ + n) * 4] =
            make_float4(o01.x, o01.y, o23.x, o23.y);
    }
}

// ---------------------------------------------------------------------------
extern "C" void kernel_launch(void* const* d_in, const int* in_sizes, int n_in,
                              void* d_out, int out_size)
{
    const float* xyz  = (const float*)d_in[0];
    const float* grid = (const float*)d_in[1];
    const float* w1   = (const float*)d_in[2];
    const float* b1   = (const float*)d_in[3];
    const float* w2   = (const float*)d_in[4];
    const float* b2   = (const float*)d_in[5];
    float* out = (float*)d_out;

    const int smem_bytes = 17540 * 4;  // 70160 B dynamic SMEM
    cudaFuncSetAttribute(latent_kernel,
                         cudaFuncAttributeMaxDynamicSharedMemorySize, smem_bytes);

    dim3 gt(W_ / 64, H_, B_);
    transpose_kernel<<<gt, 256>>>(grid);
    latent_kernel<<<B_ * TPB, 256, smem_bytes>>>(xyz, w1, b1, w2, b2, out);
}